// round 14
// baseline (speedup 1.0000x reference)
#include <cuda_runtime.h>
#include <stdint.h>

// ============================================================================
// SpecAugment, bit-exact vs JAX threefry2x32 (partitionable mode).
// R14: 256-bit memory ops. sm_100 supports v8.b32 LDG/STG (the R11 ptxas
// error explicitly allows .L2::evict_last on .v8.b32). Loads become
// ld.global.nc.L2::evict_last.v8.b32, stores st.global.cs.v8.b32:
// half the LSU issues per byte, 32B/thread/transaction, integer SEL masking.
// Everything else (RNG, mask build, grid, launch bounds) = verified R13.
// ============================================================================

#define BATCH 64
#define NMELS 80
#define TLEN 4000
#define NQ8 (TLEN / 8)         // 500 8-float groups per row
#define CHUNKS 16
#define ROWS_PER_BLK (NMELS / CHUNKS)   // 5

// ---------------- threefry2x32, constexpr-capable ----------------
struct U2 { uint32_t a, b; };

__host__ __device__ constexpr uint32_t rotl32c(uint32_t x, int d) {
    return (x << d) | (x >> (32 - d));
}

__host__ __device__ constexpr U2 tf2x32(uint32_t k0, uint32_t k1,
                                        uint32_t c0, uint32_t c1) {
    const uint32_t ks0 = k0, ks1 = k1, ks2 = 0x1BD11BDAu ^ k0 ^ k1;
    uint32_t x0 = c0 + ks0, x1 = c1 + ks1;
#define TF_RND(r) { x0 += x1; x1 = rotl32c(x1, r); x1 ^= x0; }
    TF_RND(13) TF_RND(15) TF_RND(26) TF_RND(6)
    x0 += ks1; x1 += ks2 + 1u;
    TF_RND(17) TF_RND(29) TF_RND(16) TF_RND(24)
    x0 += ks2; x1 += ks0 + 2u;
    TF_RND(13) TF_RND(15) TF_RND(26) TF_RND(6)
    x0 += ks0; x1 += ks1 + 3u;
    TF_RND(17) TF_RND(29) TF_RND(16) TF_RND(24)
    x0 += ks1; x1 += ks2 + 4u;
    TF_RND(13) TF_RND(15) TF_RND(26) TF_RND(6)
    x0 += ks2; x1 += ks0 + 5u;
#undef TF_RND
    return U2{x0, x1};
}

// Compile-time key folds: split(key(42), 4) and randint's internal split.
constexpr U2 KFW = tf2x32(0u, 42u, 0u, 0u);            // kf_w
constexpr U2 KFS = tf2x32(0u, 42u, 0u, 1u);            // kf_s
constexpr U2 KTW = tf2x32(0u, 42u, 0u, 2u);            // kt_w
constexpr U2 KTS = tf2x32(0u, 42u, 0u, 3u);            // kt_s
constexpr U2 KLO = tf2x32(KFW.a, KFW.b, 0u, 1u);       // randint lower-bits key

__device__ __forceinline__ uint32_t randbits32(uint32_t k0, uint32_t k1, uint32_t idx) {
    U2 r = tf2x32(k0, k1, 0u, idx);
    return r.a ^ r.b;
}

__device__ __forceinline__ float u32_to_unif(uint32_t bits) {
    return __uint_as_float((bits >> 9) | 0x3f800000u) - 1.0f;
}

// ---------------- 256-bit global memory ops ----------------
struct V8 { uint32_t r[8]; };

// mel load: read-only, L2 high-retention, 32 bytes. Non-volatile (pure).
__device__ __forceinline__ V8 ldg256_el(const uint32_t* p) {
    V8 v;
    asm("ld.global.nc.L2::evict_last.v8.b32 {%0,%1,%2,%3,%4,%5,%6,%7}, [%8];"
        : "=r"(v.r[0]), "=r"(v.r[1]), "=r"(v.r[2]), "=r"(v.r[3]),
          "=r"(v.r[4]), "=r"(v.r[5]), "=r"(v.r[6]), "=r"(v.r[7])
        : "l"(p));
    return v;
}

__device__ __forceinline__ void stg256_cs(uint32_t* p, const V8& v) {
    asm volatile("st.global.cs.v8.b32 [%0], {%1,%2,%3,%4,%5,%6,%7,%8};"
                 :: "l"(p),
                    "r"(v.r[0]), "r"(v.r[1]), "r"(v.r[2]), "r"(v.r[3]),
                    "r"(v.r[4]), "r"(v.r[5]), "r"(v.r[6]), "r"(v.r[7])
                 : "memory");
}

// ---------------- fused kernel ----------------
__global__ void __launch_bounds__(256, 8)
fused_kernel(const float* __restrict__ mel,
             const int* __restrict__ lengths,
             float* __restrict__ out) {
    __shared__ int s_t0[5], s_tl[5], s_f0[2], s_fl[2];
    __shared__ uint32_t s_bits[TLEN / 32];   // 4000 bits = 125 words

    const int b = blockIdx.x >> 4;        // batch
    const int chunk = blockIdx.x & 15;    // 5-row chunk within batch
    const int tid = threadIdx.x;

    // -- RNG draws (identical math to verified R1-R13) --
    if (tid < 5) {
        int j = tid;
        int valid = lengths[b];
        int mt = (int)((float)valid * 0.05f);
        int max_t = min(25, mt);
        max_t = min(max_t, valid - 1);
        max_t = max(0, max_t);
        uint32_t i = (uint32_t)(b * 5 + j);
        float ut = u32_to_unif(randbits32(KTW.a, KTW.b, i));
        int t = (int)floorf(ut * (float)(max_t + 1));
        if (valid <= 1) t = 0;
        float ut0 = u32_to_unif(randbits32(KTS.a, KTS.b, i));
        int t0 = (int)floorf(ut0 * (float)(valid - t + 1));
        s_t0[j] = t0;
        s_tl[j] = t;
    } else if (tid < 7) {
        int j = tid - 5;
        uint32_t i = (uint32_t)(b * 2 + j);
        int f = (int)(randbits32(KLO.a, KLO.b, i) & 15u);
        float uf = u32_to_unif(randbits32(KFS.a, KFS.b, i));
        int f0 = (int)floorf(uf * (float)(NMELS - f + 1));
        s_f0[j] = f0;
        s_fl[j] = f;
    }
    __syncthreads();

    // -- build 4000-bit time mask via interval spans --
    if (tid < TLEN / 32) {
        const int base = tid * 32;
        uint32_t w = 0;
#pragma unroll
        for (int j = 0; j < 5; j++) {
            int lo = max(s_t0[j], base);
            int hi = min(s_t0[j] + s_tl[j], base + 32);
            if (hi > lo)
                w |= (uint32_t)(((1ull << (hi - lo)) - 1ull) << (lo - base));
        }
        s_bits[tid] = w;
    }
    __syncthreads();

    const int f00 = s_f0[0], fl0 = s_fl[0], f01 = s_f0[1], fl1 = s_fl[1];

    // -- stream 5 rows; 2 x 32B groups per thread per row --
#pragma unroll
    for (int r = 0; r < ROWS_PER_BLK; r++) {
        const int m = chunk * ROWS_PER_BLK + r;
        const int row = b * NMELS + m;
        const uint32_t* mrow = reinterpret_cast<const uint32_t*>(mel) + (size_t)row * TLEN;
        uint32_t* orow = reinterpret_cast<uint32_t*>(out) + (size_t)row * TLEN;
        const bool rz = ((unsigned)(m - f00) < (unsigned)fl0) |
                        ((unsigned)(m - f01) < (unsigned)fl1);

        if (rz) {
            V8 z;
#pragma unroll
            for (int q = 0; q < 8; q++) z.r[q] = 0u;
#pragma unroll
            for (int k = 0; k < 2; k++) {
                int idx = tid + k * 256;
                if (idx < NQ8)
                    stg256_cs(orow + idx * 8, z);
            }
        } else {
            V8 v[2];
            unsigned mb[2];
            // loads first (front-batched 32B LDGs)
#pragma unroll
            for (int k = 0; k < 2; k++) {
                int idx = tid + k * 256;
                if (idx < NQ8)
                    v[k] = ldg256_el(mrow + idx * 8);
            }
            // mask bytes while loads are in flight: 8 bits per group
#pragma unroll
            for (int k = 0; k < 2; k++) {
                int idx = tid + k * 256;
                mb[k] = (idx < NQ8)
                    ? (s_bits[idx >> 2] >> ((idx & 3) * 8)) & 255u
                    : 0u;
            }
#pragma unroll
            for (int k = 0; k < 2; k++) {
                int idx = tid + k * 256;
                if (idx >= NQ8) continue;
#pragma unroll
                for (int q = 0; q < 8; q++)
                    v[k].r[q] = (mb[k] & (1u << q)) ? 0u : v[k].r[q];
                stg256_cs(orow + idx * 8, v[k]);
            }
        }
    }
}

extern "C" void kernel_launch(void* const* d_in, const int* in_sizes, int n_in,
                              void* d_out, int out_size) {
    const float* mel = (const float*)d_in[0];
    const int* lengths = (const int*)d_in[1];
    float* out = (float*)d_out;

    fused_kernel<<<BATCH * CHUNKS, 256>>>(mel, lengths, out);
}